// round 4
// baseline (speedup 1.0000x reference)
#include <cuda_runtime.h>
#include <cuda_bf16.h>

#define E  8
#define DD 512
#define H1 512
#define H2 256
#define YD 256
#define BB 8192
#define TM 128
#define TN 64
#define TK 16
#define MAX_ROWS (BB + E * TM)        // 9216 (worst-case padded)
#define MAX_TILES (MAX_ROWS / TM)     // 72

// ---- scratch (static device globals; no allocations allowed) ----
__device__ float g_a1[MAX_ROWS * H1];   // layer-1 activations, expert-sorted
__device__ float g_a2[MAX_ROWS * H2];   // layer-2 activations, expert-sorted
__device__ int   g_perm[MAX_ROWS];      // sorted-pos -> original row (-1 = pad)
__device__ int   g_counts[E];
__device__ int   g_cursor[E];
__device__ int   g_padoff[E + 1];       // tile-aligned segment offsets
__device__ int   g_is64;                // gate dtype: 1 = int64, 0 = int32

// ---------------- routing ----------------

__global__ void route_detect(const int* __restrict__ gate32) {
    // If gate is int64 (values 0..7), every odd int32 word (high dword) is 0.
    // If gate is int32, odd words are gate values; some are nonzero w.p. ~1.
    __shared__ int any_nz;
    if (threadIdx.x == 0) any_nz = 0;
    __syncthreads();
    int v = gate32[2 * threadIdx.x + 1];   // odd indices 1..127
    if (v != 0) atomicOr(&any_nz, 1);
    __syncthreads();
    if (threadIdx.x == 0) g_is64 = (any_nz == 0) ? 1 : 0;
}

__global__ void route_setup() {
    int i = blockIdx.x * blockDim.x + threadIdx.x;
    if (i < MAX_ROWS) g_perm[i] = -1;
    if (i < E) { g_counts[i] = 0; g_cursor[i] = 0; }
}

__device__ __forceinline__ int load_gate(const int* g32, int i) {
    int e;
    if (g_is64) e = (int)((const long long*)g32)[i];
    else        e = g32[i];
    return e < 0 ? 0 : (e > E - 1 ? E - 1 : e);
}

__global__ void route_hist(const int* __restrict__ gate32) {
    int i = blockIdx.x * blockDim.x + threadIdx.x;
    if (i < BB) atomicAdd(&g_counts[load_gate(gate32, i)], 1);
}

__global__ void route_finalize() {
    if (threadIdx.x == 0 && blockIdx.x == 0) {
        int off = 0;
        for (int e = 0; e < E; e++) {
            g_padoff[e] = off;
            off += ((g_counts[e] + TM - 1) / TM) * TM;
        }
        g_padoff[E] = off;
    }
}

__global__ void route_scatter(const int* __restrict__ gate32) {
    int i = blockIdx.x * blockDim.x + threadIdx.x;
    if (i < BB) {
        int e = load_gate(gate32, i);
        int pos = g_padoff[e] + atomicAdd(&g_cursor[e], 1);
        g_perm[pos] = i;
    }
}

// ---------------- grouped GEMM ----------------
// One block = 128 rows (single expert, guaranteed by padding) x 64 cols.
// 256 threads, 8x4 register blocking, TK=16 smem tiles.
// LAYER 1: A = gather(h, perm)  [K=512] -> leaky -> g_a1     [N=512]
// LAYER 2: A = g_a1 (sorted)    [K=512] -> leaky -> g_a2     [N=256]
// LAYER 3: A = g_a2 (sorted)    [K=256] -> +bias -> scatter out [N=256]

template <int LAYER>
__global__ void __launch_bounds__(256) expert_gemm(
    const float* __restrict__ Ain,     // h for layer 1 (else unused)
    const float* __restrict__ W,
    const float* __restrict__ bias,
    float* __restrict__ OutG)          // d_out for layer 3 (else unused)
{
    constexpr int K = (LAYER == 3) ? H2 : DD;
    constexpr int N = (LAYER == 1) ? H1 : H2;

    const int row0 = blockIdx.y * TM;
    if (row0 >= g_padoff[E]) return;
    const int n0 = blockIdx.x * TN;

    int e = 0;
    #pragma unroll
    for (int j = 1; j < E; j++)
        if (row0 >= g_padoff[j]) e = j;

    const float* A;
    if (LAYER == 1)      A = Ain;
    else if (LAYER == 2) A = g_a1;
    else                 A = g_a2;
    const float* Wp = W + (size_t)e * K * N;
    const float* bp = bias + (size_t)e * N;

    __shared__ float As[TK][TM];
    __shared__ float Bs[TK][TN];

    const int tid = threadIdx.x;
    const int tx = tid & 15;     // col group (4 cols)
    const int ty = tid >> 4;     // row group (8 rows)

    // Pre-resolve gather rows for the two A-load slots (layer 1 only).
    int grow0 = 0, grow1 = 0;
    if (LAYER == 1) {
        grow0 = g_perm[row0 + (tid & 127)];
        grow1 = g_perm[row0 + ((tid + 256) & 127)];
    }

    float acc[8][4];
    #pragma unroll
    for (int i = 0; i < 8; i++)
        #pragma unroll
        for (int j = 0; j < 4; j++) acc[i][j] = 0.0f;

    const int bkc = tid >> 4;    // B-tile k row
    const int bnq = tid & 15;    // B-tile col quad

    for (int k0 = 0; k0 < K; k0 += TK) {
        __syncthreads();
        // ---- A tile: 128 rows x 16 k, transposed into As[k][m] ----
        #pragma unroll
        for (int s = 0; s < 2; s++) {
            const int q  = tid + s * 256;
            const int kq = q >> 7;        // which float4 along k (0..3)
            const int rl = q & 127;       // local row
            float4 v;
            if (LAYER == 1) {
                const int grow = (s == 0) ? grow0 : grow1;
                if (grow >= 0)
                    v = *(const float4*)(A + (size_t)grow * K + k0 + kq * 4);
                else
                    v = make_float4(0.f, 0.f, 0.f, 0.f);
            } else {
                v = *(const float4*)(A + (size_t)(row0 + rl) * K + k0 + kq * 4);
            }
            As[kq * 4 + 0][rl] = v.x;
            As[kq * 4 + 1][rl] = v.y;
            As[kq * 4 + 2][rl] = v.z;
            As[kq * 4 + 3][rl] = v.w;
        }
        // ---- B tile: 16 k x 64 n (W is K-major, coalesced) ----
        {
            float4 v = *(const float4*)(Wp + (size_t)(k0 + bkc) * N + n0 + bnq * 4);
            *(float4*)&Bs[bkc][bnq * 4] = v;
        }
        __syncthreads();
        // ---- compute ----
        #pragma unroll
        for (int kc = 0; kc < TK; kc++) {
            const float4 a0 = *(const float4*)&As[kc][ty * 8];
            const float4 a1 = *(const float4*)&As[kc][ty * 8 + 4];
            const float4 b0 = *(const float4*)&Bs[kc][tx * 4];
            const float ar[8] = {a0.x, a0.y, a0.z, a0.w, a1.x, a1.y, a1.z, a1.w};
            const float br[4] = {b0.x, b0.y, b0.z, b0.w};
            #pragma unroll
            for (int i = 0; i < 8; i++)
                #pragma unroll
                for (int j = 0; j < 4; j++)
                    acc[i][j] = fmaf(ar[i], br[j], acc[i][j]);
        }
    }

    // ---- epilogue ----
    if (LAYER == 3) {
        #pragma unroll
        for (int i = 0; i < 8; i++) {
            const int rl = ty * 8 + i;
            const int orig = g_perm[row0 + rl];
            if (orig >= 0) {
                #pragma unroll
                for (int j = 0; j < 4; j++) {
                    const int col = n0 + tx * 4 + j;
                    OutG[(size_t)orig * N + col] = acc[i][j] + bp[col];
                }
            }
        }
    } else {
        float* dst = (LAYER == 1) ? g_a1 : g_a2;
        #pragma unroll
        for (int i = 0; i < 8; i++) {
            const int rl = ty * 8 + i;
            #pragma unroll
            for (int j = 0; j < 4; j++) {
                const int col = n0 + tx * 4 + j;
                float v = acc[i][j] + bp[col];
                v = (v > 0.0f) ? v : 0.2f * v;
                dst[(size_t)(row0 + rl) * N + col] = v;
            }
        }
    }
}

// ---------------- launch ----------------

extern "C" void kernel_launch(void* const* d_in, const int* in_sizes, int n_in,
                              void* d_out, int out_size) {
    const float* h    = (const float*)d_in[0];
    const int*   gate = (const int*)  d_in[1];   // width detected on device
    const float* W1   = (const float*)d_in[2];
    const float* b1   = (const float*)d_in[3];
    const float* W2   = (const float*)d_in[4];
    const float* b2   = (const float*)d_in[5];
    const float* W3   = (const float*)d_in[6];
    const float* b3   = (const float*)d_in[7];
    float* out = (float*)d_out;

    route_detect<<<1, 64>>>(gate);
    route_setup<<<(MAX_ROWS + 255) / 256, 256>>>();
    route_hist<<<(BB + 255) / 256, 256>>>(gate);
    route_finalize<<<1, 1>>>();
    route_scatter<<<(BB + 255) / 256, 256>>>(gate);

    dim3 g1(H1 / TN, MAX_TILES);
    expert_gemm<1><<<g1, 256>>>(h, W1, b1, nullptr);
    dim3 g2(H2 / TN, MAX_TILES);
    expert_gemm<2><<<g2, 256>>>(nullptr, W2, b2, nullptr);
    dim3 g3(YD / TN, MAX_TILES);
    expert_gemm<3><<<g3, 256>>>(nullptr, W3, b3, out);
}

// round 6
// speedup vs baseline: 2.3212x; 2.3212x over previous
#include <cuda_runtime.h>
#include <cuda_bf16.h>
#include <cstdint>

#define E  8
#define DD 512
#define H1 512
#define H2 256
#define YD 256
#define BB 8192
#define TM 128
#define MAX_ROWS (BB + E * TM)        // 9216
#define MAX_TILES (MAX_ROWS / TM)     // 72

// ===================== helpers =====================
__device__ __forceinline__ uint32_t smem_u32(const void* p) {
    uint32_t a;
    asm("{ .reg .u64 t; cvta.to.shared.u64 t, %1; cvt.u32.u64 %0, t; }" : "=r"(a) : "l"(p));
    return a;
}
__device__ __forceinline__ void cp16(uint32_t dst, const void* src) {
    asm volatile("cp.async.cg.shared.global [%0], [%1], 16;" :: "r"(dst), "l"(src));
}
__device__ __forceinline__ void cp_commit() {
    asm volatile("cp.async.commit_group;" ::: "memory");
}
template <int N>
__device__ __forceinline__ void cp_wait() {
    asm volatile("cp.async.wait_group %0;" :: "n"(N) : "memory");
}
__device__ __forceinline__ void ldsm4(uint32_t* r, uint32_t addr) {
    asm volatile("ldmatrix.sync.aligned.m8n8.x4.shared.b16 {%0,%1,%2,%3}, [%4];"
        : "=r"(r[0]), "=r"(r[1]), "=r"(r[2]), "=r"(r[3]) : "r"(addr));
}
__device__ __forceinline__ void mma16816(float* c, const uint32_t* a, const uint32_t* b) {
    asm volatile("mma.sync.aligned.m16n8k16.row.col.f32.bf16.bf16.f32 "
        "{%0,%1,%2,%3}, {%4,%5,%6,%7}, {%8,%9}, {%0,%1,%2,%3};"
        : "+f"(c[0]), "+f"(c[1]), "+f"(c[2]), "+f"(c[3])
        : "r"(a[0]), "r"(a[1]), "r"(a[2]), "r"(a[3]), "r"(b[0]), "r"(b[1]));
}
__device__ __forceinline__ uint32_t pk2(__nv_bfloat16 a, __nv_bfloat16 b) {
    return (uint32_t)__bfloat16_as_ushort(a) | ((uint32_t)__bfloat16_as_ushort(b) << 16);
}

// ===================== scratch =====================
__device__ __nv_bfloat16 g_Ah[MAX_ROWS * DD],  g_Al[MAX_ROWS * DD];
__device__ __nv_bfloat16 g_a1h[MAX_ROWS * H1], g_a1l[MAX_ROWS * H1];
__device__ __nv_bfloat16 g_a2h[MAX_ROWS * H2], g_a2l[MAX_ROWS * H2];
__device__ __nv_bfloat16 g_W1h[E * H1 * DD],   g_W1l[E * H1 * DD];   // [e][n][k]
__device__ __nv_bfloat16 g_W2h[E * H2 * H1],   g_W2l[E * H2 * H1];
__device__ __nv_bfloat16 g_W3h[E * YD * H2],   g_W3l[E * YD * H2];
__device__ int g_perm[MAX_ROWS];
__device__ int g_counts[E];
__device__ int g_cursor[E];
__device__ int g_padoff[E + 1];
__device__ int g_is64;

// ===================== routing =====================
__global__ void route_detect(const int* __restrict__ gate32) {
    __shared__ int any_nz;
    if (threadIdx.x == 0) any_nz = 0;
    __syncthreads();
    int v = gate32[2 * threadIdx.x + 1];
    if (v != 0) atomicOr(&any_nz, 1);
    __syncthreads();
    if (threadIdx.x == 0) g_is64 = (any_nz == 0) ? 1 : 0;
}
__global__ void route_setup() {
    int i = blockIdx.x * blockDim.x + threadIdx.x;
    if (i < MAX_ROWS) g_perm[i] = -1;
    if (i < E) { g_counts[i] = 0; g_cursor[i] = 0; }
}
__device__ __forceinline__ int load_gate(const int* g32, int i) {
    int e = g_is64 ? (int)((const long long*)g32)[i] : g32[i];
    return e < 0 ? 0 : (e > E - 1 ? E - 1 : e);
}
__global__ void route_hist(const int* __restrict__ gate32) {
    int i = blockIdx.x * blockDim.x + threadIdx.x;
    if (i < BB) atomicAdd(&g_counts[load_gate(gate32, i)], 1);
}
__global__ void route_finalize() {
    if (threadIdx.x == 0 && blockIdx.x == 0) {
        int off = 0;
        for (int e = 0; e < E; e++) {
            g_padoff[e] = off;
            off += ((g_counts[e] + TM - 1) / TM) * TM;
        }
        g_padoff[E] = off;
    }
}
__global__ void route_scatter(const int* __restrict__ gate32) {
    int i = blockIdx.x * blockDim.x + threadIdx.x;
    if (i < BB) {
        int e = load_gate(gate32, i);
        g_perm[g_padoff[e] + atomicAdd(&g_cursor[e], 1)] = i;
    }
}

// ===================== fp32 -> bf16 hi/lo conversions =====================
// weights: [E][K][N] -> hi/lo [E][N][K] (tiled transpose)
__global__ void conv_w(const float* __restrict__ W, __nv_bfloat16* __restrict__ Wh,
                       __nv_bfloat16* __restrict__ Wl, int K, int N) {
    __shared__ float s[32][33];
    const int e = blockIdx.z;
    const float* Wp = W + (size_t)e * K * N;
    const int n0 = blockIdx.x * 32, k0 = blockIdx.y * 32;
    #pragma unroll
    for (int i = 0; i < 32; i += 8)
        s[threadIdx.y + i][threadIdx.x] = Wp[(size_t)(k0 + threadIdx.y + i) * N + n0 + threadIdx.x];
    __syncthreads();
    #pragma unroll
    for (int i = 0; i < 32; i += 8) {
        const int n = threadIdx.y + i, k = threadIdx.x;
        float v = s[k][n];
        __nv_bfloat16 h = __float2bfloat16(v);
        __nv_bfloat16 l = __float2bfloat16(v - __bfloat162float(h));
        size_t o = ((size_t)e * N + n0 + n) * (size_t)K + k0 + k;
        Wh[o] = h; Wl[o] = l;
    }
}
// layer-1 A: gather h rows via perm, split hi/lo
__global__ void conv_a(const float* __restrict__ h) {
    int idx = blockIdx.x * 256 + threadIdx.x;
    if (idx >= MAX_ROWS * (DD / 4)) return;
    int p = idx >> 7, kq = idx & 127;
    int orig = g_perm[p];
    float4 v = make_float4(0.f, 0.f, 0.f, 0.f);
    if (orig >= 0) v = *(const float4*)(h + (size_t)orig * DD + kq * 4);
    __nv_bfloat16 h0 = __float2bfloat16(v.x), h1 = __float2bfloat16(v.y);
    __nv_bfloat16 h2 = __float2bfloat16(v.z), h3 = __float2bfloat16(v.w);
    __nv_bfloat16 l0 = __float2bfloat16(v.x - __bfloat162float(h0));
    __nv_bfloat16 l1 = __float2bfloat16(v.y - __bfloat162float(h1));
    __nv_bfloat16 l2 = __float2bfloat16(v.z - __bfloat162float(h2));
    __nv_bfloat16 l3 = __float2bfloat16(v.w - __bfloat162float(h3));
    size_t o = (size_t)p * DD + kq * 4;
    *(uint2*)(g_Ah + o) = make_uint2(pk2(h0, h1), pk2(h2, h3));
    *(uint2*)(g_Al + o) = make_uint2(pk2(l0, l1), pk2(l2, l3));
}

// ===================== warp-MMA grouped GEMM =====================
// CTA 128x128, 8 warps (4 in M x 2 in N), warp tile 32x64.
// K chunks of 64 bf16 (128B rows, SW128 swizzle), cp.async double-buffered.
// Split-3: acc += Ah*Bh + Ah*Bl + Al*Bh.
// MODE 0: bias+leaky -> bf16 hi/lo.  MODE 1: bias -> fp32 scatter via perm.

#define MAT 16384                     // one 128x128B matrix tile
#define BUF (4 * MAT)                 // Ah, Al, Bh, Bl
#define GEMM_SMEM (2 * BUF)           // 131072

template <int K, int NT, int MODE>
__global__ void __launch_bounds__(256, 1) moe_gemm(
    const __nv_bfloat16* __restrict__ Ah, const __nv_bfloat16* __restrict__ Al,
    const __nv_bfloat16* __restrict__ Bh, const __nv_bfloat16* __restrict__ Bl,
    const float* __restrict__ bias,
    __nv_bfloat16* __restrict__ Oh, __nv_bfloat16* __restrict__ Ol,
    float* __restrict__ Of)
{
    const int row0 = blockIdx.y * TM;
    if (row0 >= g_padoff[E]) return;
    const int n0 = blockIdx.x * 128;

    int e = 0;
    #pragma unroll
    for (int j = 1; j < E; j++)
        if (row0 >= g_padoff[j]) e = j;

    extern __shared__ char smem[];
    const uint32_t sbase = smem_u32(smem);
    const int tid = threadIdx.x;
    const int wid = tid >> 5, lane = tid & 31;
    const int wm = wid & 3, wn = wid >> 2;    // 4 x 2 warp grid

    const __nv_bfloat16* Ahp = Ah + (size_t)row0 * K;
    const __nv_bfloat16* Alp = Al + (size_t)row0 * K;
    const __nv_bfloat16* Bhp = Bh + ((size_t)e * NT + n0) * (size_t)K;
    const __nv_bfloat16* Blp = Bl + ((size_t)e * NT + n0) * (size_t)K;

    constexpr int C = K / 64;

    // loader precompute: 4 segments/thread/matrix per chunk
    const int lr[4] = { (tid + 0)   >> 3, (tid + 256) >> 3,
                        (tid + 512) >> 3, (tid + 768) >> 3 };
    const int lseg  = tid & 7;
    uint32_t lso[4];
    #pragma unroll
    for (int s = 0; s < 4; s++)
        lso[s] = (uint32_t)(lr[s] * 128 + ((lseg ^ (lr[s] & 7)) << 4));

    auto load_chunk = [&](int c, int buf) {
        const uint32_t sb = sbase + buf * BUF;
        #pragma unroll
        for (int s = 0; s < 4; s++) {
            const size_t go = (size_t)lr[s] * K + c * 64 + lseg * 8;
            cp16(sb + lso[s],           Ahp + go);
            cp16(sb + MAT + lso[s],     Alp + go);
            cp16(sb + 2 * MAT + lso[s], Bhp + go);
            cp16(sb + 3 * MAT + lso[s], Blp + go);
        }
        cp_commit();
    };

    // ldmatrix address precompute
    const int arow_lo = wm * 32 + (lane & 15);       // + mi*16
    const int akh = lane >> 4;                        // k half
    const int nrow_lo = (lane & 7) + ((lane >> 4) << 3);  // + np*16
    const int bkh = (lane >> 3) & 1;

    float acc[2][8][4];
    #pragma unroll
    for (int mi = 0; mi < 2; mi++)
        #pragma unroll
        for (int ni = 0; ni < 8; ni++)
            #pragma unroll
            for (int q = 0; q < 4; q++) acc[mi][ni][q] = 0.f;

    load_chunk(0, 0);

    for (int c = 0; c < C; c++) {
        if (c + 1 < C) { load_chunk(c + 1, (c + 1) & 1); cp_wait<1>(); }
        else cp_wait<0>();
        __syncthreads();

        const uint32_t sb = sbase + (c & 1) * BUF;
        #pragma unroll
        for (int ks = 0; ks < 4; ks++) {
            uint32_t ah[2][4], al[2][4];
            #pragma unroll
            for (int mi = 0; mi < 2; mi++) {
                const int r = arow_lo + mi * 16;
                const int seg = ks * 2 + akh;
                const uint32_t off = (uint32_t)(r * 128 + ((seg ^ (r & 7)) << 4));
                ldsm4(ah[mi], sb + off);
                ldsm4(al[mi], sb + MAT + off);
            }
            uint32_t bh[8][2], bl[8][2];
            #pragma unroll
            for (int np = 0; np < 4; np++) {
                const int r = wn * 64 + np * 16 + nrow_lo;
                const int seg = ks * 2 + bkh;
                const uint32_t off = (uint32_t)(r * 128 + ((seg ^ (r & 7)) << 4));
                uint32_t t4[4];
                ldsm4(t4, sb + 2 * MAT + off);
                bh[np * 2][0] = t4[0]; bh[np * 2][1] = t4[1];
                bh[np * 2 + 1][0] = t4[2]; bh[np * 2 + 1][1] = t4[3];
                ldsm4(t4, sb + 3 * MAT + off);
                bl[np * 2][0] = t4[0]; bl[np * 2][1] = t4[1];
                bl[np * 2 + 1][0] = t4[2]; bl[np * 2 + 1][1] = t4[3];
            }
            #pragma unroll
            for (int mi = 0; mi < 2; mi++)
                #pragma unroll
                for (int ni = 0; ni < 8; ni++) {
                    mma16816(acc[mi][ni], ah[mi], bh[ni]);
                    mma16816(acc[mi][ni], ah[mi], bl[ni]);
                    mma16816(acc[mi][ni], al[mi], bh[ni]);
                }
        }
        __syncthreads();
    }

    // ---- epilogue ----
    const float* bp = bias + (size_t)e * NT;
    const int qrow = lane >> 2;           // 0..7
    const int qcol = (lane & 3) * 2;

    #pragma unroll
    for (int mi = 0; mi < 2; mi++) {
        #pragma unroll
        for (int rh = 0; rh < 2; rh++) {
            const int rl = wm * 32 + mi * 16 + qrow + rh * 8;
            const int grow = row0 + rl;
            int orig = 0;
            if (MODE == 1) orig = g_perm[grow];
            #pragma unroll
            for (int ni = 0; ni < 8; ni++) {
                const int col = n0 + wn * 64 + ni * 8 + qcol;
                const float2 bb = *(const float2*)(bp + col);
                float v0 = acc[mi][ni][rh * 2 + 0] + bb.x;
                float v1 = acc[mi][ni][rh * 2 + 1] + bb.y;
                if (MODE == 0) {
                    v0 = v0 > 0.f ? v0 : 0.2f * v0;
                    v1 = v1 > 0.f ? v1 : 0.2f * v1;
                    __nv_bfloat16 h0 = __float2bfloat16(v0), h1 = __float2bfloat16(v1);
                    __nv_bfloat16 l0 = __float2bfloat16(v0 - __bfloat162float(h0));
                    __nv_bfloat16 l1 = __float2bfloat16(v1 - __bfloat162float(h1));
                    *(uint32_t*)(Oh + (size_t)grow * NT + col) = pk2(h0, h1);
                    *(uint32_t*)(Ol + (size_t)grow * NT + col) = pk2(l0, l1);
                } else {
                    if (orig >= 0)
                        *(float2*)(Of + (size_t)orig * NT + col) = make_float2(v0, v1);
                }
            }
        }
    }
}

// ===================== launch =====================
extern "C" void kernel_launch(void* const* d_in, const int* in_sizes, int n_in,
                              void* d_out, int out_size) {
    const float* h    = (const float*)d_in[0];
    const int*   gate = (const int*)  d_in[1];
    const float* W1   = (const float*)d_in[2];
    const float* b1   = (const float*)d_in[3];
    const float* W2   = (const float*)d_in[4];
    const float* b2   = (const float*)d_in[5];
    const float* W3   = (const float*)d_in[6];
    const float* b3   = (const float*)d_in[7];
    float* out = (float*)d_out;

    cudaFuncSetAttribute(moe_gemm<DD, H1, 0>, cudaFuncAttributeMaxDynamicSharedMemorySize, GEMM_SMEM);
    cudaFuncSetAttribute(moe_gemm<H1, H2, 0>, cudaFuncAttributeMaxDynamicSharedMemorySize, GEMM_SMEM);
    cudaFuncSetAttribute(moe_gemm<H2, YD, 1>, cudaFuncAttributeMaxDynamicSharedMemorySize, GEMM_SMEM);

    // routing
    route_detect<<<1, 64>>>(gate);
    route_setup<<<(MAX_ROWS + 255) / 256, 256>>>();
    route_hist<<<(BB + 255) / 256, 256>>>(gate);
    route_finalize<<<1, 1>>>();
    route_scatter<<<(BB + 255) / 256, 256>>>(gate);

    // operand conversion
    __nv_bfloat16 *ah, *al, *a1h, *a1l, *a2h, *a2l, *w1h, *w1l, *w2h, *w2l, *w3h, *w3l;
    cudaGetSymbolAddress((void**)&ah,  g_Ah);  cudaGetSymbolAddress((void**)&al,  g_Al);
    cudaGetSymbolAddress((void**)&a1h, g_a1h); cudaGetSymbolAddress((void**)&a1l, g_a1l);
    cudaGetSymbolAddress((void**)&a2h, g_a2h); cudaGetSymbolAddress((void**)&a2l, g_a2l);
    cudaGetSymbolAddress((void**)&w1h, g_W1h); cudaGetSymbolAddress((void**)&w1l, g_W1l);
    cudaGetSymbolAddress((void**)&w2h, g_W2h); cudaGetSymbolAddress((void**)&w2l, g_W2l);
    cudaGetSymbolAddress((void**)&w3h, g_W3h); cudaGetSymbolAddress((void**)&w3l, g_W3l);

    conv_w<<<dim3(H1 / 32, DD / 32, E), dim3(32, 8)>>>(W1, w1h, w1l, DD, H1);
    conv_w<<<dim3(H2 / 32, H1 / 32, E), dim3(32, 8)>>>(W2, w2h, w2l, H1, H2);
    conv_w<<<dim3(YD / 32, H2 / 32, E), dim3(32, 8)>>>(W3, w3h, w3l, H2, YD);
    conv_a<<<(MAX_ROWS * (DD / 4) + 255) / 256, 256>>>(h);

    // grouped GEMMs
    moe_gemm<DD, H1, 0><<<dim3(H1 / 128, MAX_TILES), 256, GEMM_SMEM>>>(
        ah, al, w1h, w1l, b1, a1h, a1l, nullptr);
    moe_gemm<H1, H2, 0><<<dim3(H2 / 128, MAX_TILES), 256, GEMM_SMEM>>>(
        a1h, a1l, w2h, w2l, b2, a2h, a2l, nullptr);
    moe_gemm<H2, YD, 1><<<dim3(YD / 128, MAX_TILES), 256, GEMM_SMEM>>>(
        a2h, a2l, w3h, w3l, b3, nullptr, nullptr, out);
}

// round 7
// speedup vs baseline: 2.4551x; 1.0577x over previous
#include <cuda_runtime.h>
#include <cuda_bf16.h>
#include <cstdint>

#define E  8
#define DD 512
#define H1 512
#define H2 256
#define YD 256
#define BB 8192
#define TM 128
#define MAX_ROWS (BB + E * TM)        // 9216
#define MAX_TILES (MAX_ROWS / TM)     // 72

// ===================== helpers =====================
__device__ __forceinline__ uint32_t smem_u32(const void* p) {
    uint32_t a;
    asm("{ .reg .u64 t; cvta.to.shared.u64 t, %1; cvt.u32.u64 %0, t; }" : "=r"(a) : "l"(p));
    return a;
}
__device__ __forceinline__ void cp16(uint32_t dst, const void* src) {
    asm volatile("cp.async.cg.shared.global [%0], [%1], 16;" :: "r"(dst), "l"(src));
}
__device__ __forceinline__ void cp_commit() {
    asm volatile("cp.async.commit_group;" ::: "memory");
}
template <int N>
__device__ __forceinline__ void cp_wait() {
    asm volatile("cp.async.wait_group %0;" :: "n"(N) : "memory");
}
__device__ __forceinline__ void ldsm4(uint32_t* r, uint32_t addr) {
    asm volatile("ldmatrix.sync.aligned.m8n8.x4.shared.b16 {%0,%1,%2,%3}, [%4];"
        : "=r"(r[0]), "=r"(r[1]), "=r"(r[2]), "=r"(r[3]) : "r"(addr));
}
__device__ __forceinline__ void mma16816(float* c, const uint32_t* a, const uint32_t* b) {
    asm volatile("mma.sync.aligned.m16n8k16.row.col.f32.bf16.bf16.f32 "
        "{%0,%1,%2,%3}, {%4,%5,%6,%7}, {%8,%9}, {%0,%1,%2,%3};"
        : "+f"(c[0]), "+f"(c[1]), "+f"(c[2]), "+f"(c[3])
        : "r"(a[0]), "r"(a[1]), "r"(a[2]), "r"(a[3]), "r"(b[0]), "r"(b[1]));
}
__device__ __forceinline__ uint32_t pk2(__nv_bfloat16 a, __nv_bfloat16 b) {
    return (uint32_t)__bfloat16_as_ushort(a) | ((uint32_t)__bfloat16_as_ushort(b) << 16);
}

// ===================== scratch =====================
__device__ __nv_bfloat16 g_Ah[MAX_ROWS * DD],  g_Al[MAX_ROWS * DD];
__device__ __nv_bfloat16 g_a1h[MAX_ROWS * H1], g_a1l[MAX_ROWS * H1];
__device__ __nv_bfloat16 g_a2h[MAX_ROWS * H2], g_a2l[MAX_ROWS * H2];
__device__ __nv_bfloat16 g_W1h[E * H1 * DD],   g_W1l[E * H1 * DD];   // [e][n][k]
__device__ __nv_bfloat16 g_W2h[E * H2 * H1],   g_W2l[E * H2 * H1];
__device__ __nv_bfloat16 g_W3h[E * YD * H2],   g_W3l[E * YD * H2];
__device__ int g_perm[MAX_ROWS];
__device__ int g_padoff[E + 1];

// ===================== fused routing (one CTA) =====================
__global__ void __launch_bounds__(1024) route_all(const int* __restrict__ gate32) {
    __shared__ int s_cnt[E], s_off[E + 1], s_cur[E], s_nz;
    const int tid = threadIdx.x;
    if (tid == 0) s_nz = 0;
    if (tid < E) { s_cnt[tid] = 0; s_cur[tid] = 0; }
    __syncthreads();
    // dtype detect: int64 gate of values 0..7 has all-zero odd words
    if (tid < 512 && gate32[2 * tid + 1] != 0) atomicOr(&s_nz, 1);
    __syncthreads();
    const int is64 = (s_nz == 0);

    auto gate = [&](int i) -> int {
        int e = is64 ? (int)((const long long*)gate32)[i] : gate32[i];
        return e < 0 ? 0 : (e > E - 1 ? E - 1 : e);
    };

    // init perm + histogram (different arrays, safe to interleave)
    for (int i = tid; i < MAX_ROWS; i += 1024) g_perm[i] = -1;
    for (int i = tid; i < BB; i += 1024) atomicAdd(&s_cnt[gate(i)], 1);
    __syncthreads();

    if (tid == 0) {
        int off = 0;
        #pragma unroll
        for (int e = 0; e < E; e++) {
            s_off[e] = off; g_padoff[e] = off;
            off += ((s_cnt[e] + TM - 1) / TM) * TM;
        }
        s_off[E] = off; g_padoff[E] = off;
    }
    __syncthreads();

    for (int i = tid; i < BB; i += 1024) {
        int e = gate(i);
        g_perm[s_off[e] + atomicAdd(&s_cur[e], 1)] = i;
    }
}

// ===================== fused weight conversion =====================
// [E][K][N] -> hi/lo [E][N][K], 32x32 tiles, all three weights in one grid.
// W1: 8*16*16 = 2048 blocks; W2: 8*16*8 = 1024; W3: 8*8*8 = 512. Total 3584.
__global__ void conv_w_all(const float* __restrict__ W1, const float* __restrict__ W2,
                           const float* __restrict__ W3) {
    __shared__ float s[32][33];
    const int b = blockIdx.x;
    const float* W; __nv_bfloat16 *Wh, *Wl;
    int K, N, e, kt, nt;
    if (b < 2048) {
        W = W1; Wh = g_W1h; Wl = g_W1l; K = DD; N = H1;
        e = b >> 8; kt = (b >> 4) & 15; nt = b & 15;
    } else if (b < 3072) {
        const int r = b - 2048;
        W = W2; Wh = g_W2h; Wl = g_W2l; K = H1; N = H2;
        e = r >> 7; kt = (r >> 3) & 15; nt = r & 7;
    } else {
        const int r = b - 3072;
        W = W3; Wh = g_W3h; Wl = g_W3l; K = H2; N = YD;
        e = r >> 6; kt = (r >> 3) & 7; nt = r & 7;
    }
    const float* Wp = W + (size_t)e * K * N;
    const int n0 = nt * 32, k0 = kt * 32;
    #pragma unroll
    for (int i = 0; i < 32; i += 8)
        s[threadIdx.y + i][threadIdx.x] = Wp[(size_t)(k0 + threadIdx.y + i) * N + n0 + threadIdx.x];
    __syncthreads();
    #pragma unroll
    for (int i = 0; i < 32; i += 8) {
        const int n = threadIdx.y + i, k = threadIdx.x;
        float v = s[k][n];
        __nv_bfloat16 h = __float2bfloat16(v);
        __nv_bfloat16 l = __float2bfloat16(v - __bfloat162float(h));
        size_t o = ((size_t)e * N + n0 + n) * (size_t)K + k0 + k;
        Wh[o] = h; Wl[o] = l;
    }
}

// layer-1 A: gather h rows via perm, split hi/lo
__global__ void conv_a(const float* __restrict__ h) {
    int idx = blockIdx.x * 256 + threadIdx.x;
    if (idx >= MAX_ROWS * (DD / 4)) return;
    int p = idx >> 7, kq = idx & 127;
    int orig = g_perm[p];
    float4 v = make_float4(0.f, 0.f, 0.f, 0.f);
    if (orig >= 0) v = *(const float4*)(h + (size_t)orig * DD + kq * 4);
    __nv_bfloat16 h0 = __float2bfloat16(v.x), h1 = __float2bfloat16(v.y);
    __nv_bfloat16 h2 = __float2bfloat16(v.z), h3 = __float2bfloat16(v.w);
    __nv_bfloat16 l0 = __float2bfloat16(v.x - __bfloat162float(h0));
    __nv_bfloat16 l1 = __float2bfloat16(v.y - __bfloat162float(h1));
    __nv_bfloat16 l2 = __float2bfloat16(v.z - __bfloat162float(h2));
    __nv_bfloat16 l3 = __float2bfloat16(v.w - __bfloat162float(h3));
    size_t o = (size_t)p * DD + kq * 4;
    *(uint2*)(g_Ah + o) = make_uint2(pk2(h0, h1), pk2(h2, h3));
    *(uint2*)(g_Al + o) = make_uint2(pk2(l0, l1), pk2(l2, l3));
}

// ===================== warp-MMA grouped GEMM =====================
// CTA 128x128, 8 warps (4 in M x 2 in N), warp tile 32x64.
// K chunks of 64 bf16 (128B rows, SW128 swizzle), cp.async double-buffered.
// Split-3: acc += Ah*Bh + Ah*Bl + Al*Bh.
// MODE 0: bias+leaky -> bf16 hi/lo.  MODE 1: bias -> fp32 scatter via perm.

#define MAT 16384                     // one 128x128B matrix tile
#define BUF (4 * MAT)                 // Ah, Al, Bh, Bl
#define GEMM_SMEM (2 * BUF)           // 131072

template <int K, int NT, int MODE>
__global__ void __launch_bounds__(256, 1) moe_gemm(
    const __nv_bfloat16* __restrict__ Ah, const __nv_bfloat16* __restrict__ Al,
    const __nv_bfloat16* __restrict__ Bh, const __nv_bfloat16* __restrict__ Bl,
    const float* __restrict__ bias,
    __nv_bfloat16* __restrict__ Oh, __nv_bfloat16* __restrict__ Ol,
    float* __restrict__ Of)
{
    const int row0 = blockIdx.y * TM;
    if (row0 >= g_padoff[E]) return;
    const int n0 = blockIdx.x * 128;

    int e = 0;
    #pragma unroll
    for (int j = 1; j < E; j++)
        if (row0 >= g_padoff[j]) e = j;

    extern __shared__ char smem[];
    const uint32_t sbase = smem_u32(smem);
    const int tid = threadIdx.x;
    const int wid = tid >> 5, lane = tid & 31;
    const int wm = wid & 3, wn = wid >> 2;    // 4 x 2 warp grid

    const __nv_bfloat16* Ahp = Ah + (size_t)row0 * K;
    const __nv_bfloat16* Alp = Al + (size_t)row0 * K;
    const __nv_bfloat16* Bhp = Bh + ((size_t)e * NT + n0) * (size_t)K;
    const __nv_bfloat16* Blp = Bl + ((size_t)e * NT + n0) * (size_t)K;

    constexpr int C = K / 64;

    const int lr[4] = { (tid + 0)   >> 3, (tid + 256) >> 3,
                        (tid + 512) >> 3, (tid + 768) >> 3 };
    const int lseg  = tid & 7;
    uint32_t lso[4];
    #pragma unroll
    for (int s = 0; s < 4; s++)
        lso[s] = (uint32_t)(lr[s] * 128 + ((lseg ^ (lr[s] & 7)) << 4));

    auto load_chunk = [&](int c, int buf) {
        const uint32_t sb = sbase + buf * BUF;
        #pragma unroll
        for (int s = 0; s < 4; s++) {
            const size_t go = (size_t)lr[s] * K + c * 64 + lseg * 8;
            cp16(sb + lso[s],           Ahp + go);
            cp16(sb + MAT + lso[s],     Alp + go);
            cp16(sb + 2 * MAT + lso[s], Bhp + go);
            cp16(sb + 3 * MAT + lso[s], Blp + go);
        }
        cp_commit();
    };

    const int arow_lo = wm * 32 + (lane & 15);
    const int akh = lane >> 4;
    const int nrow_lo = (lane & 7) + ((lane >> 4) << 3);
    const int bkh = (lane >> 3) & 1;

    float acc[2][8][4];
    #pragma unroll
    for (int mi = 0; mi < 2; mi++)
        #pragma unroll
        for (int ni = 0; ni < 8; ni++)
            #pragma unroll
            for (int q = 0; q < 4; q++) acc[mi][ni][q] = 0.f;

    load_chunk(0, 0);

    for (int c = 0; c < C; c++) {
        if (c + 1 < C) { load_chunk(c + 1, (c + 1) & 1); cp_wait<1>(); }
        else cp_wait<0>();
        __syncthreads();

        const uint32_t sb = sbase + (c & 1) * BUF;
        #pragma unroll
        for (int ks = 0; ks < 4; ks++) {
            uint32_t ah[2][4], al[2][4];
            #pragma unroll
            for (int mi = 0; mi < 2; mi++) {
                const int r = arow_lo + mi * 16;
                const int seg = ks * 2 + akh;
                const uint32_t off = (uint32_t)(r * 128 + ((seg ^ (r & 7)) << 4));
                ldsm4(ah[mi], sb + off);
                ldsm4(al[mi], sb + MAT + off);
            }
            uint32_t bh[8][2], bl[8][2];
            #pragma unroll
            for (int np = 0; np < 4; np++) {
                const int r = wn * 64 + np * 16 + nrow_lo;
                const int seg = ks * 2 + bkh;
                const uint32_t off = (uint32_t)(r * 128 + ((seg ^ (r & 7)) << 4));
                uint32_t t4[4];
                ldsm4(t4, sb + 2 * MAT + off);
                bh[np * 2][0] = t4[0]; bh[np * 2][1] = t4[1];
                bh[np * 2 + 1][0] = t4[2]; bh[np * 2 + 1][1] = t4[3];
                ldsm4(t4, sb + 3 * MAT + off);
                bl[np * 2][0] = t4[0]; bl[np * 2][1] = t4[1];
                bl[np * 2 + 1][0] = t4[2]; bl[np * 2 + 1][1] = t4[3];
            }
            #pragma unroll
            for (int mi = 0; mi < 2; mi++)
                #pragma unroll
                for (int ni = 0; ni < 8; ni++) {
                    mma16816(acc[mi][ni], ah[mi], bh[ni]);
                    mma16816(acc[mi][ni], ah[mi], bl[ni]);
                    mma16816(acc[mi][ni], al[mi], bh[ni]);
                }
        }
        __syncthreads();
    }

    // ---- epilogue ----
    const float* bp = bias + (size_t)e * NT;
    const int qrow = lane >> 2;
    const int qcol = (lane & 3) * 2;

    #pragma unroll
    for (int mi = 0; mi < 2; mi++) {
        #pragma unroll
        for (int rh = 0; rh < 2; rh++) {
            const int rl = wm * 32 + mi * 16 + qrow + rh * 8;
            const int grow = row0 + rl;
            int orig = 0;
            if (MODE == 1) orig = g_perm[grow];
            #pragma unroll
            for (int ni = 0; ni < 8; ni++) {
                const int col = n0 + wn * 64 + ni * 8 + qcol;
                const float2 bb = *(const float2*)(bp + col);
                float v0 = acc[mi][ni][rh * 2 + 0] + bb.x;
                float v1 = acc[mi][ni][rh * 2 + 1] + bb.y;
                if (MODE == 0) {
                    v0 = v0 > 0.f ? v0 : 0.2f * v0;
                    v1 = v1 > 0.f ? v1 : 0.2f * v1;
                    __nv_bfloat16 h0 = __float2bfloat16(v0), h1 = __float2bfloat16(v1);
                    __nv_bfloat16 l0 = __float2bfloat16(v0 - __bfloat162float(h0));
                    __nv_bfloat16 l1 = __float2bfloat16(v1 - __bfloat162float(h1));
                    *(uint32_t*)(Oh + (size_t)grow * NT + col) = pk2(h0, h1);
                    *(uint32_t*)(Ol + (size_t)grow * NT + col) = pk2(l0, l1);
                } else {
                    if (orig >= 0)
                        *(float2*)(Of + (size_t)orig * NT + col) = make_float2(v0, v1);
                }
            }
        }
    }
}

// ===================== launch =====================
extern "C" void kernel_launch(void* const* d_in, const int* in_sizes, int n_in,
                              void* d_out, int out_size) {
    const float* h    = (const float*)d_in[0];
    const int*   gate = (const int*)  d_in[1];
    const float* W1   = (const float*)d_in[2];
    const float* b1   = (const float*)d_in[3];
    const float* W2   = (const float*)d_in[4];
    const float* b2   = (const float*)d_in[5];
    const float* W3   = (const float*)d_in[6];
    const float* b3   = (const float*)d_in[7];
    float* out = (float*)d_out;

    cudaFuncSetAttribute(moe_gemm<DD, H1, 0>, cudaFuncAttributeMaxDynamicSharedMemorySize, GEMM_SMEM);
    cudaFuncSetAttribute(moe_gemm<H1, H2, 0>, cudaFuncAttributeMaxDynamicSharedMemorySize, GEMM_SMEM);
    cudaFuncSetAttribute(moe_gemm<H2, YD, 1>, cudaFuncAttributeMaxDynamicSharedMemorySize, GEMM_SMEM);

    __nv_bfloat16 *ah, *al, *a1h, *a1l, *a2h, *a2l, *w1h, *w1l, *w2h, *w2l, *w3h, *w3l;
    cudaGetSymbolAddress((void**)&ah,  g_Ah);  cudaGetSymbolAddress((void**)&al,  g_Al);
    cudaGetSymbolAddress((void**)&a1h, g_a1h); cudaGetSymbolAddress((void**)&a1l, g_a1l);
    cudaGetSymbolAddress((void**)&a2h, g_a2h); cudaGetSymbolAddress((void**)&a2l, g_a2l);
    cudaGetSymbolAddress((void**)&w1h, g_W1h); cudaGetSymbolAddress((void**)&w1l, g_W1l);
    cudaGetSymbolAddress((void**)&w2h, g_W2h); cudaGetSymbolAddress((void**)&w2l, g_W2l);
    cudaGetSymbolAddress((void**)&w3h, g_W3h); cudaGetSymbolAddress((void**)&w3l, g_W3l);

    route_all<<<1, 1024>>>(gate);
    conv_w_all<<<3584, dim3(32, 8)>>>(W1, W2, W3);
    conv_a<<<(MAX_ROWS * (DD / 4) + 255) / 256, 256>>>(h);

    moe_gemm<DD, H1, 0><<<dim3(H1 / 128, MAX_TILES), 256, GEMM_SMEM>>>(
        ah, al, w1h, w1l, b1, a1h, a1l, nullptr);
    moe_gemm<H1, H2, 0><<<dim3(H2 / 128, MAX_TILES), 256, GEMM_SMEM>>>(
        a1h, a1l, w2h, w2l, b2, a2h, a2l, nullptr);
    moe_gemm<H2, YD, 1><<<dim3(YD / 128, MAX_TILES), 256, GEMM_SMEM>>>(
        a2h, a2l, w3h, w3l, b3, nullptr, nullptr, out);
}